// round 4
// baseline (speedup 1.0000x reference)
#include <cuda_runtime.h>
#include <math.h>

// Problem constants
#define Bb    2
#define Ll    8192
#define DMm   256
#define NHh   4
#define HPp   64
#define NSs   8
#define DPROJ 532          // 2*DIN + 2*NS + NH
#define ZXW   1064         // 2*DPROJ
#define ZXS   1088         // padded row stride for zx scratch
#define Mrows (Bb*Ll)      // 16384
#define LC    32           // scan chunk length
#define NCc   (Ll/LC)      // 256 chunks

// ---------------- scratch (static device memory; no allocations) -------------
__device__ __align__(16) float g_zxH[(size_t)Mrows * ZXS];
__device__ __align__(16) float g_zxV[(size_t)Mrows * ZXS];
__device__ __align__(16) float g_E  [(size_t)4 * Bb * NHh * NCc * HPp * NSs];
__device__ __align__(16) float g_S0 [(size_t)4 * Bb * NHh * NCc * HPp * NSs];
__device__ __align__(16) float g_P  [4 * Bb * NHh * NCc];
__device__ __align__(16) float g_ydir[(size_t)4 * Bb * Ll * DMm];
__device__ __align__(16) float g_cat [(size_t)Mrows * 1024];
__device__ float g_dtb[4][NHh];
__device__ float g_Aco[4][NHh];   // -exp(A_log) * log2(e)  (for exp2f)
__device__ float g_Dv [4][NHh];

// ---------------- helpers ----------------------------------------------------
__device__ __forceinline__ float silu_f(float x) {
    float e = __expf(-x);
    return __fdividef(x, 1.0f + e);
}
__device__ __forceinline__ float softplus_f(float x) {
    return (x > 20.0f) ? x : log1pf(__expf(x));
}
__device__ __forceinline__ unsigned tf32b(float x) {
    unsigned u;
    asm("cvt.rna.tf32.f32 %0, %1;" : "=r"(u) : "f"(x));
    return u;
}

struct PtrPack { const float* q[12]; };  // dtb[4], A_log[4], D[4]

__global__ void k_prep(PtrPack pp) {
    int i = threadIdx.x;
    if (i < 16) {
        int d = i >> 2, h = i & 3;
        g_dtb[d][h] = pp.q[d][h];
        g_Aco[d][h] = -expf(pp.q[4 + d][h]) * 1.44269504f;
        g_Dv [d][h] = pp.q[8 + d][h];
    }
}

// ---------------- tf32 tensor-core GEMM (batched over blockIdx.z) ------------
// C[M,*] = A[M,K] @ W[K,Nw], fp32 accumulate, tf32 inputs.
// Block tile 128x128, BK=16, 256 threads = 8 warps (4M x 2N), warp tile 32x64.
// epiMode: 0 = plain, 1 = silu, 2 = zx preactivation (silu cols c<528 within
// each DPROJ half, softplus(+dt_bias[z*2+half]) on dt cols 528..531).
#define AP 136
#define TFMMA_SMEM (2 * 2 * 16 * AP * 4)

struct GB { const float* A[4]; const float* W[4]; float* C[4]; };

#define MMA_TF32(ac, af, bf)                                              \
    asm volatile(                                                          \
        "mma.sync.aligned.m16n8k8.row.col.f32.tf32.tf32.f32 "              \
        "{%0,%1,%2,%3}, {%4,%5,%6,%7}, {%8,%9}, {%0,%1,%2,%3};"            \
        : "+f"(ac[0]), "+f"(ac[1]), "+f"(ac[2]), "+f"(ac[3])               \
        : "r"(af[0]), "r"(af[1]), "r"(af[2]), "r"(af[3]),                  \
          "r"(bf[0]), "r"(bf[1]))

__device__ __forceinline__ float epi_apply(float v, int col, int mode, int z) {
    if (mode == 0) return v;
    if (mode == 1) return silu_f(v);
    int half = (col >= DPROJ) ? 1 : 0;
    int c = col - half * DPROJ;
    if (c < 528) return silu_f(v);
    return softplus_f(v + g_dtb[z * 2 + half][c - 528]);
}

__global__ __launch_bounds__(256, 1) void k_tfmma(
    GB gb, int lda, int ldw, int Nw, int ldc, int Nstore, int K, int epiMode)
{
    extern __shared__ float sm[];
    float* As = sm;                    // [2][16][AP]
    float* Ws = sm + 2 * 16 * AP;      // [2][16][AP]

    const int zi   = blockIdx.z;
    const float* __restrict__ A = gb.A[zi];
    const float* __restrict__ W = gb.W[zi];
    float* __restrict__ C = gb.C[zi];

    const int tid  = threadIdx.x;
    const int lane = tid & 31;
    const int warp = tid >> 5;
    const int wm = (warp & 3) * 32;
    const int wn = (warp >> 2) * 64;
    const int g = lane >> 2;
    const int q = lane & 3;
    const int m0 = blockIdx.y * 128;
    const int n0 = blockIdx.x * 128;

    float acc[2][8][4];
#pragma unroll
    for (int mi = 0; mi < 2; mi++)
#pragma unroll
        for (int ni = 0; ni < 8; ni++)
#pragma unroll
            for (int r = 0; r < 4; r++) acc[mi][ni][r] = 0.0f;

    float4 va[2], vw[2];

#define LOAD_TILES(k0)                                                        \
    {                                                                         \
        _Pragma("unroll")                                                     \
        for (int it = 0; it < 2; ++it) {                                      \
            int idx = tid + (it << 8);                                        \
            int row = idx >> 2, kk = (idx & 3) << 2;                          \
            va[it] = *(const float4*)(A + (size_t)(m0 + row) * lda + (k0) + kk); \
            int wk = idx >> 5, nc = (idx & 31) << 2;                          \
            int gc = n0 + nc;                                                 \
            float4 wv = make_float4(0.f, 0.f, 0.f, 0.f);                      \
            if (gc < Nw)                                                      \
                wv = *(const float4*)(W + (size_t)((k0) + wk) * ldw + gc);    \
            vw[it] = wv;                                                      \
        }                                                                     \
    }

#define STORE_TILES(buf)                                                      \
    {                                                                         \
        _Pragma("unroll")                                                     \
        for (int it = 0; it < 2; ++it) {                                      \
            int idx = tid + (it << 8);                                        \
            int row = idx >> 2, kk = (idx & 3) << 2;                          \
            float4 av = va[it];                                               \
            float* ap = As + ((buf) * 16 + kk) * AP + row;                    \
            ap[0 * AP] = __uint_as_float(tf32b(av.x));                        \
            ap[1 * AP] = __uint_as_float(tf32b(av.y));                        \
            ap[2 * AP] = __uint_as_float(tf32b(av.z));                        \
            ap[3 * AP] = __uint_as_float(tf32b(av.w));                        \
            int wk = idx >> 5, nc = (idx & 31) << 2;                          \
            float4 wv = vw[it];                                               \
            float4 wt;                                                        \
            wt.x = __uint_as_float(tf32b(wv.x));                              \
            wt.y = __uint_as_float(tf32b(wv.y));                              \
            wt.z = __uint_as_float(tf32b(wv.z));                              \
            wt.w = __uint_as_float(tf32b(wv.w));                              \
            *(float4*)(Ws + ((buf) * 16 + wk) * AP + nc) = wt;                \
        }                                                                     \
    }

    LOAD_TILES(0);
    STORE_TILES(0);
    __syncthreads();

    const int nIter = K >> 4;
    for (int itk = 0; itk < nIter; ++itk) {
        const int buf = itk & 1;
        if (itk + 1 < nIter) LOAD_TILES((itk + 1) << 4);

#pragma unroll
        for (int kg = 0; kg < 2; ++kg) {
            const float* Ab = As + (buf * 16 + kg * 8 + q) * AP;
            const float* Bb_ = Ws + (buf * 16 + kg * 8 + q) * AP;
            unsigned af[2][4];
#pragma unroll
            for (int mi = 0; mi < 2; mi++) {
                int row = wm + mi * 16 + g;
                af[mi][0] = __float_as_uint(Ab[row]);
                af[mi][1] = __float_as_uint(Ab[row + 8]);
                af[mi][2] = __float_as_uint(Ab[4 * AP + row]);
                af[mi][3] = __float_as_uint(Ab[4 * AP + row + 8]);
            }
            unsigned bf[8][2];
#pragma unroll
            for (int ni = 0; ni < 8; ni++) {
                int col = wn + ni * 8 + g;
                bf[ni][0] = __float_as_uint(Bb_[col]);
                bf[ni][1] = __float_as_uint(Bb_[4 * AP + col]);
            }
#pragma unroll
            for (int mi = 0; mi < 2; mi++)
#pragma unroll
                for (int ni = 0; ni < 8; ni++)
                    MMA_TF32(acc[mi][ni], af[mi], bf[ni]);
        }

        if (itk + 1 < nIter) STORE_TILES(buf ^ 1);
        __syncthreads();
    }

#pragma unroll
    for (int mi = 0; mi < 2; mi++) {
        int row = m0 + wm + mi * 16 + g;
#pragma unroll
        for (int ni = 0; ni < 8; ni++) {
            int col = n0 + wn + ni * 8 + q * 2;
            if (col < Nstore) {
                float2 v0, v1;
                v0.x = epi_apply(acc[mi][ni][0], col,     epiMode, zi);
                v0.y = epi_apply(acc[mi][ni][1], col + 1, epiMode, zi);
                v1.x = epi_apply(acc[mi][ni][2], col,     epiMode, zi);
                v1.y = epi_apply(acc[mi][ni][3], col + 1, epiMode, zi);
                *(float2*)(C + (size_t)row * ldc + col) = v0;
                *(float2*)(C + (size_t)(row + 8) * ldc + col) = v1;
            }
        }
    }
}

// ---------------- scan pass 1: per-chunk local scan (pure FMA now) -----------
// zx rows are preactivated: x/B/C silu'd, dt softplus'ed (bias added).
__global__ __launch_bounds__(64) void k_scan1() {
    const int c  = blockIdx.x;
    const int b  = blockIdx.y >> 2;
    const int h  = blockIdx.y & 3;
    const int d  = blockIdx.z;
    const int p  = threadIdx.x;
    const float* zx = (d < 2) ? g_zxH : g_zxV;
    const int off = (d & 1) * DPROJ;
    const int rev = d & 1;

    __shared__ float sa[LC];
    __shared__ float sdtB[LC][NSs];
    __shared__ float sx[LC][HPp];

    if (p < LC) {
        int t = rev ? (Ll - 1 - (c * LC + p)) : (c * LC + p);
        const float* row = zx + (size_t)(b * Ll + t) * ZXS + off;
        float dt = row[528 + h];
        sa[p] = exp2f(dt * g_Aco[d][h]);
#pragma unroll
        for (int n = 0; n < NSs; n++) sdtB[p][n] = dt * row[512 + n];
    }
#pragma unroll 8
    for (int i = 0; i < LC; i++) {
        int t = rev ? (Ll - 1 - (c * LC + i)) : (c * LC + i);
        sx[i][p] = zx[(size_t)(b * Ll + t) * ZXS + off + 256 + h * HPp + p];
    }
    __syncthreads();

    float s[NSs];
#pragma unroll
    for (int n = 0; n < NSs; n++) s[n] = 0.0f;
    float pr = 1.0f;
#pragma unroll 4
    for (int i = 0; i < LC; i++) {
        float a = sa[i];
        float xv = sx[i][p];
        pr *= a;
#pragma unroll
        for (int n = 0; n < NSs; n++) s[n] = fmaf(a, s[n], sdtB[i][n] * xv);
    }
    size_t base = ((((size_t)d * Bb + b) * NHh + h) * NCc + c);
    float* Ep = g_E + base * HPp * NSs + p * NSs;
#pragma unroll
    for (int n = 0; n < NSs; n++) Ep[n] = s[n];
    if (p == 0) g_P[base] = pr;
}

// ---------------- scan pass 2: combine chunk summaries -----------------------
__global__ __launch_bounds__(64) void k_scan2() {
    const int bid = blockIdx.x;      // 32 blocks: d*8 + b*4 + h
    const int d = bid >> 3, b = (bid >> 2) & 1, h = bid & 3;
    const int p = threadIdx.x;
    size_t base = (((size_t)d * Bb + b) * NHh + h) * NCc;

    __shared__ float sP[NCc];
    for (int c = p; c < NCc; c += 64) sP[c] = g_P[base + c];
    __syncthreads();

    float s[NSs];
#pragma unroll
    for (int n = 0; n < NSs; n++) s[n] = 0.0f;
#pragma unroll 2
    for (int c = 0; c < NCc; c++) {
        float* S0p = g_S0 + (base + c) * HPp * NSs + p * NSs;
        const float* Ep = g_E + (base + c) * HPp * NSs + p * NSs;
        float P = sP[c];
#pragma unroll
        for (int n = 0; n < NSs; n++) {
            S0p[n] = s[n];
            s[n] = fmaf(P, s[n], Ep[n]);
        }
    }
}

// ---------------- scan pass 3: replay with true init state, emit y -----------
__global__ __launch_bounds__(64) void k_scan3(const int* __restrict__ v2h) {
    const int c  = blockIdx.x;
    const int b  = blockIdx.y >> 2;
    const int h  = blockIdx.y & 3;
    const int d  = blockIdx.z;
    const int p  = threadIdx.x;
    const float* zx = (d < 2) ? g_zxH : g_zxV;
    const int off = (d & 1) * DPROJ;
    const int rev = d & 1;

    __shared__ float sa[LC];
    __shared__ float sdtB[LC][NSs];
    __shared__ float sC[LC][NSs];
    __shared__ float sx[LC][HPp];

    if (p < LC) {
        int t = rev ? (Ll - 1 - (c * LC + p)) : (c * LC + p);
        const float* row = zx + (size_t)(b * Ll + t) * ZXS + off;
        float dt = row[528 + h];
        sa[p] = exp2f(dt * g_Aco[d][h]);
#pragma unroll
        for (int n = 0; n < NSs; n++) {
            sdtB[p][n] = dt * row[512 + n];
            sC[p][n]   = row[520 + n];
        }
    }
#pragma unroll 8
    for (int i = 0; i < LC; i++) {
        int t = rev ? (Ll - 1 - (c * LC + i)) : (c * LC + i);
        sx[i][p] = zx[(size_t)(b * Ll + t) * ZXS + off + 256 + h * HPp + p];
    }
    __syncthreads();

    size_t base = ((((size_t)d * Bb + b) * NHh + h) * NCc + c);
    const float* S0p = g_S0 + base * HPp * NSs + p * NSs;
    float s[NSs];
#pragma unroll
    for (int n = 0; n < NSs; n++) s[n] = S0p[n];
    const float Dh = g_Dv[d][h];
    const size_t ybase = (((size_t)d * Bb + b) * Ll);

#pragma unroll 4
    for (int i = 0; i < LC; i++) {
        int t = rev ? (Ll - 1 - (c * LC + i)) : (c * LC + i);
        float a = sa[i];
        float xv = sx[i][p];
#pragma unroll
        for (int n = 0; n < NSs; n++) s[n] = fmaf(a, s[n], sdtB[i][n] * xv);
        float y = 0.0f;
#pragma unroll
        for (int n = 0; n < NSs; n++) y = fmaf(s[n], sC[i][n], y);
        // z column is presilu'd in zx; direct coalesced load (not in the chain)
        float zv = zx[(size_t)(b * Ll + t) * ZXS + off + h * HPp + p];
        float out = (y + Dh * xv) * zv;
        int trow = (d >= 2) ? v2h[b * Ll + t] : t;
        g_ydir[(ybase + trow) * DMm + h * HPp + p] = out;
    }
}

// ---------------- launch -----------------------------------------------------
extern "C" void kernel_launch(void* const* d_in, const int* in_sizes, int n_in,
                              void* d_out, int out_size) {
    const float *xH, *xV, *WinH, *WinV, *WoHF, *WoHB, *WoVF, *WoVB, *Wout;
    const float *dtb[4], *alog[4], *Dp[4];
    const int* v2h;

    if (in_sizes[4] > 1000) {
        xH   = (const float*)d_in[0];  xV   = (const float*)d_in[1];
        WinH = (const float*)d_in[2];  WinV = (const float*)d_in[3];
        WoHF = (const float*)d_in[4];  WoHB = (const float*)d_in[5];
        WoVF = (const float*)d_in[6];  WoVB = (const float*)d_in[7];
        Wout = (const float*)d_in[8];
        for (int d = 0; d < 4; d++) {
            dtb[d]  = (const float*)d_in[9 + 3 * d];
            alog[d] = (const float*)d_in[10 + 3 * d];
            Dp[d]   = (const float*)d_in[11 + 3 * d];
        }
        v2h = (const int*)d_in[21];
    } else {
        xH   = (const float*)d_in[0];  xV   = (const float*)d_in[1];
        WinH = (const float*)d_in[2];  WinV = (const float*)d_in[3];
        for (int d = 0; d < 4; d++) {
            dtb[d]  = (const float*)d_in[4 + d];
            alog[d] = (const float*)d_in[8 + d];
            Dp[d]   = (const float*)d_in[12 + d];
        }
        WoHF = (const float*)d_in[16]; WoHB = (const float*)d_in[17];
        WoVF = (const float*)d_in[18]; WoVB = (const float*)d_in[19];
        Wout = (const float*)d_in[20];
        v2h  = (const int*)d_in[21];
    }

    float *zxH, *zxV, *ydir, *cat;
    cudaGetSymbolAddress((void**)&zxH,  g_zxH);
    cudaGetSymbolAddress((void**)&zxV,  g_zxV);
    cudaGetSymbolAddress((void**)&ydir, g_ydir);
    cudaGetSymbolAddress((void**)&cat,  g_cat);

    cudaFuncSetAttribute(k_tfmma, cudaFuncAttributeMaxDynamicSharedMemorySize,
                         TFMMA_SMEM);

    PtrPack pp;
    for (int d = 0; d < 4; d++) {
        pp.q[d]     = dtb[d];
        pp.q[4 + d] = alog[d];
        pp.q[8 + d] = Dp[d];
    }
    k_prep<<<1, 16>>>(pp);

    // Input projections (batched H/V) with fused activation epilogue (mode 2)
    {
        GB gb = {};
        gb.A[0] = xH;  gb.A[1] = xV;
        gb.W[0] = WinH; gb.W[1] = WinV;
        gb.C[0] = zxH; gb.C[1] = zxV;
        k_tfmma<<<dim3(9, Mrows / 128, 2), 256, TFMMA_SMEM>>>(
            gb, DMm, ZXW, ZXW, ZXS, ZXW, DMm, 2);
    }

    // Chunked linear scan (4 directions fused per launch)
    k_scan1<<<dim3(NCc, Bb * NHh, 4), 64>>>();
    k_scan2<<<32, 64>>>();
    k_scan3<<<dim3(NCc, Bb * NHh, 4), 64>>>(v2h);

    // Output projections (batched over 4 dirs), silu fused into epilogue
    // Pairing: y_HF@W_out_HB, y_HB@W_out_HF, y_VF@W_out_VB, y_VB@W_out_VF
    {
        GB gb = {};
        const float* Wsel[4] = {WoHB, WoHF, WoVB, WoVF};
        for (int d = 0; d < 4; d++) {
            gb.A[d] = ydir + (size_t)d * Bb * Ll * DMm;
            gb.W[d] = Wsel[d];
            gb.C[d] = cat + d * DMm;
        }
        k_tfmma<<<dim3(2, Mrows / 128, 4), 256, TFMMA_SMEM>>>(
            gb, DMm, DMm, DMm, 1024, DMm, DMm, 1);
    }

    // Final: (pre-silu'd) cat @ W_out -> out
    {
        GB gb = {};
        gb.A[0] = cat; gb.W[0] = Wout; gb.C[0] = (float*)d_out;
        k_tfmma<<<dim3(2, Mrows / 128, 1), 256, TFMMA_SMEM>>>(
            gb, 1024, DMm, DMm, DMm, DMm, 1024, 0);
    }
}